// round 4
// baseline (speedup 1.0000x reference)
#include <cuda_runtime.h>
#include <math.h>

#define NNODES 100000
#define RREL 3
#define EEDGES 500000
#define NETOT (RREL * EEDGES)
#define HHEADS 4
#define FFEAT 64
#define INFEAT 256
#define HF 256
#define HFTOT 768
#define NEG_SLOPE 0.2f

// ---------------- scratch (device globals) ----------------
__device__ float g_z[(long)RREL * NNODES * HF];   // 307 MB
__device__ float g_el[RREL * NNODES * HHEADS];
__device__ float g_er[RREL * NNODES * HHEADS];
__device__ int   g_cnt[NNODES];
__device__ int   g_off[NNODES + 1];
__device__ int   g_eid[NETOT];

// ---------------- CSR build ----------------
__global__ void k_zero_cnt() {
    int i = blockIdx.x * blockDim.x + threadIdx.x;
    if (i < NNODES) g_cnt[i] = 0;
}

__global__ void k_hist(const int* __restrict__ dst) {
    int e = blockIdx.x * blockDim.x + threadIdx.x;
    if (e < NETOT) atomicAdd(&g_cnt[dst[e]], 1);
}

// single-block exclusive scan (1024 threads, chunked)
__global__ void k_scan() {
    __shared__ int s[1024];
    __shared__ int carry_s;
    int tid = threadIdx.x;
    if (tid == 0) carry_s = 0;
    __syncthreads();
    for (int base = 0; base < NNODES; base += 1024) {
        int i = base + tid;
        int v = (i < NNODES) ? g_cnt[i] : 0;
        s[tid] = v;
        __syncthreads();
        #pragma unroll
        for (int o = 1; o < 1024; o <<= 1) {
            int t = (tid >= o) ? s[tid - o] : 0;
            __syncthreads();
            s[tid] += t;
            __syncthreads();
        }
        int carry = carry_s;
        if (i < NNODES) g_off[i] = carry + s[tid] - v;
        int total = s[1023];
        __syncthreads();
        if (tid == 0) carry_s = carry + total;
        __syncthreads();
    }
    if (tid == 0) g_off[NNODES] = carry_s;
}

// scatter edge ids; mutates g_off[d] -> end offset (== orig g_off[d+1])
__global__ void k_scatter(const int* __restrict__ dst) {
    int e = blockIdx.x * blockDim.x + threadIdx.x;
    if (e >= NETOT) return;
    int pos = atomicAdd(&g_off[dst[e]], 1);
    g_eid[pos] = e;
}

// ---------------- fused GEMM (all relations) + el/er epilogue --------------
#define GBM 128
#define GBN 128
#define GBK 16

__global__ void k_gemm(const float* __restrict__ x, const float* __restrict__ W,
                       const float* __restrict__ attn_l, const float* __restrict__ attn_r) {
    __shared__ float As[GBK][GBM];
    __shared__ float Bs[GBK][GBN];

    const int bm   = blockIdx.x * GBM;
    const int gcol = blockIdx.y * GBN;
    const int r    = gcol >> 8;
    const int bn   = gcol & 255;
    const float* Wr = W + (long)r * INFEAT * HF;

    const int tid = threadIdx.x;
    const int tr  = tid >> 4;
    const int tc  = tid & 15;

    float acc[8][8] = {};
    float4 aR[2], bR[2];

    {
        #pragma unroll
        for (int q = 0; q < 2; q++) {
            int i = tid + q * 256;
            int row = i >> 2, c4 = (i & 3) << 2;
            int gr = bm + row;
            aR[q] = make_float4(0.f, 0.f, 0.f, 0.f);
            if (gr < NNODES) aR[q] = *(const float4*)&x[(long)gr * INFEAT + c4];
            int brow = i >> 5, bc4 = (i & 31) << 2;
            bR[q] = *(const float4*)&Wr[brow * HF + bn + bc4];
        }
    }

    for (int k0 = 0; k0 < INFEAT; k0 += GBK) {
        #pragma unroll
        for (int q = 0; q < 2; q++) {
            int i = tid + q * 256;
            int row = i >> 2, c4 = (i & 3) << 2;
            As[c4 + 0][row] = aR[q].x; As[c4 + 1][row] = aR[q].y;
            As[c4 + 2][row] = aR[q].z; As[c4 + 3][row] = aR[q].w;
            int brow = i >> 5, bc4 = (i & 31) << 2;
            *(float4*)&Bs[brow][bc4] = bR[q];
        }
        __syncthreads();

        if (k0 + GBK < INFEAT) {
            #pragma unroll
            for (int q = 0; q < 2; q++) {
                int i = tid + q * 256;
                int row = i >> 2, c4 = (i & 3) << 2;
                int gr = bm + row;
                aR[q] = make_float4(0.f, 0.f, 0.f, 0.f);
                if (gr < NNODES) aR[q] = *(const float4*)&x[(long)gr * INFEAT + k0 + GBK + c4];
                int brow = i >> 5, bc4 = (i & 31) << 2;
                bR[q] = *(const float4*)&Wr[(k0 + GBK + brow) * HF + bn + bc4];
            }
        }

        #pragma unroll
        for (int k = 0; k < GBK; k++) {
            float a[8], b[8];
            *(float4*)&a[0] = *(float4*)&As[k][tr * 8];
            *(float4*)&a[4] = *(float4*)&As[k][tr * 8 + 4];
            *(float4*)&b[0] = *(float4*)&Bs[k][tc * 8];
            *(float4*)&b[4] = *(float4*)&Bs[k][tc * 8 + 4];
            #pragma unroll
            for (int i = 0; i < 8; i++)
                #pragma unroll
                for (int j = 0; j < 8; j++)
                    acc[i][j] = fmaf(a[i], b[j], acc[i][j]);
        }
        __syncthreads();
    }

    const int h = (bn >> 6) + (tc >> 3);
    float alv[8], arv[8];
    #pragma unroll
    for (int j = 0; j < 8; j++) {
        int col = h * FFEAT + ((tc & 7) * 8) + j;
        alv[j] = attn_l[r * HF + col];
        arv[j] = attn_r[r * HF + col];
    }

    #pragma unroll
    for (int i = 0; i < 8; i++) {
        int gr = bm + tr * 8 + i;
        bool ok = (gr < NNODES);
        if (ok) {
            float* cp = &g_z[((long)r * NNODES + gr) * HF + bn + tc * 8];
            *(float4*)cp       = *(float4*)&acc[i][0];
            *(float4*)(cp + 4) = *(float4*)&acc[i][4];
        }
        float sl = 0.f, sr = 0.f;
        #pragma unroll
        for (int j = 0; j < 8; j++) {
            sl = fmaf(acc[i][j], alv[j], sl);
            sr = fmaf(acc[i][j], arv[j], sr);
        }
        #pragma unroll
        for (int o = 4; o >= 1; o >>= 1) {
            sl += __shfl_down_sync(0xffffffffu, sl, o);
            sr += __shfl_down_sync(0xffffffffu, sr, o);
        }
        if (ok && (tc & 7) == 0) {
            g_el[((long)r * NNODES + gr) * HHEADS + h] = sl;
            g_er[((long)r * NNODES + gr) * HHEADS + h] = sr;
        }
    }
}

// ---------------- pull aggregation: 64-thread group per dst node -----------
__global__ void k_agg(const int* __restrict__ src,
                      const float* __restrict__ bias,
                      float* __restrict__ out) {
    int tid = threadIdx.x;
    int d = blockIdx.x * 4 + (tid >> 6);
    int g = tid & 63;                       // covers columns [g*4, g*4+4)
    if (d >= NNODES) return;
    int h = g >> 4;

    // post-scatter: g_off[d] = end, start = g_off[d-1] (orig off[d]); d==0 -> 0
    int off1 = g_off[d];
    int off0 = (d == 0) ? 0 : g_off[d - 1];

    float er0 = g_er[((long)0 * NNODES + d) * HHEADS + h];
    float er1 = g_er[((long)1 * NNODES + d) * HHEADS + h];
    float er2 = g_er[((long)2 * NNODES + d) * HHEADS + h];

    // pass 1: per-relation softmax denominators (head h)
    float den0 = 0.f, den1 = 0.f, den2 = 0.f;
    for (int i = off0; i < off1; i++) {
        int eid = __ldg(&g_eid[i]);
        int r = eid / EEDGES;
        int s = __ldg(&src[eid]);
        float erv = (r == 0) ? er0 : (r == 1) ? er1 : er2;
        float v = __ldg(&g_el[((long)r * NNODES + s) * HHEADS + h]) + erv;
        v = (v > 0.f) ? v : NEG_SLOPE * v;
        float ev = expf(v);
        if (r == 0) den0 += ev; else if (r == 1) den1 += ev; else den2 += ev;
    }
    float inv0 = 1.0f / den0, inv1 = 1.0f / den1, inv2 = 1.0f / den2;

    // pass 2: weighted gather
    float4 acc = make_float4(0.f, 0.f, 0.f, 0.f);
    for (int i = off0; i < off1; i++) {
        int eid = __ldg(&g_eid[i]);
        int r = eid / EEDGES;
        int s = __ldg(&src[eid]);
        float erv = (r == 0) ? er0 : (r == 1) ? er1 : er2;
        float v = __ldg(&g_el[((long)r * NNODES + s) * HHEADS + h]) + erv;
        v = (v > 0.f) ? v : NEG_SLOPE * v;
        float ev = expf(v);
        float alpha = ev * ((r == 0) ? inv0 : (r == 1) ? inv1 : inv2);
        float4 z = *(const float4*)&g_z[((long)r * NNODES + s) * HF + g * 4];
        acc.x = fmaf(alpha, z.x, acc.x);
        acc.y = fmaf(alpha, z.y, acc.y);
        acc.z = fmaf(alpha, z.z, acc.z);
        acc.w = fmaf(alpha, z.w, acc.w);
    }

    // bias (sum over relations) + ELU, single write
    int c = g * 4;
    float b0 = bias[c + 0] + bias[HF + c + 0] + bias[2 * HF + c + 0];
    float b1 = bias[c + 1] + bias[HF + c + 1] + bias[2 * HF + c + 1];
    float b2 = bias[c + 2] + bias[HF + c + 2] + bias[2 * HF + c + 2];
    float b3 = bias[c + 3] + bias[HF + c + 3] + bias[2 * HF + c + 3];
    float v0 = acc.x + b0, v1 = acc.y + b1, v2 = acc.z + b2, v3 = acc.w + b3;
    v0 = (v0 > 0.f) ? v0 : expm1f(v0);
    v1 = (v1 > 0.f) ? v1 : expm1f(v1);
    v2 = (v2 > 0.f) ? v2 : expm1f(v2);
    v3 = (v3 > 0.f) ? v3 : expm1f(v3);
    *(float4*)&out[(long)d * HF + c] = make_float4(v0, v1, v2, v3);
}

// ---------------- launch ----------------
extern "C" void kernel_launch(void* const* d_in, const int* in_sizes, int n_in,
                              void* d_out, int out_size) {
    const float* x      = (const float*)d_in[0];
    const float* W      = (const float*)d_in[1];
    const float* attn_l = (const float*)d_in[2];
    const float* attn_r = (const float*)d_in[3];
    const float* bias   = (const float*)d_in[4];
    const int*   src    = (const int*)d_in[5];   // flat [R*E]
    const int*   dst    = (const int*)d_in[6];   // flat [R*E]
    float* out = (float*)d_out;

    // GEMM first (largest kernel; CSR build is independent, runs after)
    dim3 gg((NNODES + GBM - 1) / GBM, HFTOT / GBN);
    k_gemm<<<gg, 256>>>(x, W, attn_l, attn_r);

    // CSR build (by dst, all relations combined)
    k_zero_cnt<<<(NNODES + 255) / 256, 256>>>();
    k_hist<<<(NETOT + 255) / 256, 256>>>(dst);
    k_scan<<<1, 1024>>>();
    k_scatter<<<(NETOT + 255) / 256, 256>>>(dst);

    // pull aggregation + bias + ELU (single write of out)
    k_agg<<<(NNODES + 3) / 4, 256>>>(src, bias, out);
}

// round 6
// speedup vs baseline: 1.3927x; 1.3927x over previous
#include <cuda_runtime.h>
#include <cuda_bf16.h>
#include <math.h>
#include <stdint.h>

#define NNODES 100000
#define RREL 3
#define EEDGES 500000
#define HHEADS 4
#define FFEAT 64
#define INFEAT 256
#define HF 256
#define NEG_SLOPE 0.2f

// ---------------- scratch ----------------
__device__ float g_z[(long)RREL * NNODES * HF];
__device__ float g_el[RREL * NNODES * HHEADS];
__device__ float g_er[RREL * NNODES * HHEADS];
__device__ float g_den[RREL * NNODES * HHEADS];
__device__ float g_e[(long)RREL * EEDGES * HHEADS];

// ---------------- init: zero out, den, el, er ----------------
__global__ void k_zero(float* __restrict__ out) {
    int i = blockIdx.x * blockDim.x + threadIdx.x;
    int stride = gridDim.x * blockDim.x;
    for (int j = i; j < NNODES * HF; j += stride) out[j] = 0.0f;
    for (int j = i; j < RREL * NNODES * HHEADS; j += stride) {
        g_den[j] = 0.0f;
        g_el[j] = 0.0f;
        g_er[j] = 0.0f;
    }
}

// ---------------- mma.sync helper ----------------
__device__ __forceinline__ void mma_bf16(float* c, const uint32_t* a, const uint32_t* b) {
    asm volatile(
        "mma.sync.aligned.m16n8k16.row.col.f32.bf16.bf16.f32 "
        "{%0,%1,%2,%3}, {%4,%5,%6,%7}, {%8,%9}, {%0,%1,%2,%3};"
        : "+f"(c[0]), "+f"(c[1]), "+f"(c[2]), "+f"(c[3])
        : "r"(a[0]), "r"(a[1]), "r"(a[2]), "r"(a[3]), "r"(b[0]), "r"(b[1]));
}

__device__ __forceinline__ void split_bf16(float v, __nv_bfloat16& h, __nv_bfloat16& l) {
    h = __float2bfloat16(v);
    l = __float2bfloat16(v - __bfloat162float(h));
}

// ---------------- tensor-core GEMM (bf16 split) + fused el/er --------------
#define GBM 128
#define GBN 128
#define GBK 32
#define APAD 40   // padded row length (bf16 elems) -> conflict-free frag loads

__global__ void __launch_bounds__(256)
k_gemm(const float* __restrict__ x, const float* __restrict__ W,
       const float* __restrict__ attn_l, const float* __restrict__ attn_r) {
    __shared__ __nv_bfloat16 sAh[GBM][APAD];
    __shared__ __nv_bfloat16 sAl[GBM][APAD];
    __shared__ __nv_bfloat16 sBh[GBN][APAD];
    __shared__ __nv_bfloat16 sBl[GBN][APAD];

    const int tid  = threadIdx.x;
    const int wid  = tid >> 5;
    const int lane = tid & 31;
    const int g    = lane >> 2;       // 0..7
    const int t    = lane & 3;        // 0..3
    const int bm   = blockIdx.x * GBM;
    const int bn   = blockIdx.y * GBN;
    const int r    = blockIdx.z;
    const float* Wr = W + (long)r * INFEAT * HF;

    const int mband = (wid & 1) * 64;   // warp m offset
    const int nband = (wid >> 1) * 32;  // warp n offset

    float acc[4][4][4];
    #pragma unroll
    for (int mi = 0; mi < 4; mi++)
        #pragma unroll
        for (int ni = 0; ni < 4; ni++)
            #pragma unroll
            for (int q = 0; q < 4; q++) acc[mi][ni][q] = 0.f;

    for (int k0 = 0; k0 < INFEAT; k0 += GBK) {
        __syncthreads();
        // ---- load A tile: x[bm..bm+127][k0..k0+31] -> hi/lo
        {
            const int row = tid >> 1;
            const int kb  = (tid & 1) * 16;
            const int gr  = bm + row;
            float v[16];
            if (gr < NNODES) {
                const float4* xp = (const float4*)&x[(long)gr * INFEAT + k0 + kb];
                #pragma unroll
                for (int q = 0; q < 4; q++) *(float4*)&v[q * 4] = xp[q];
            } else {
                #pragma unroll
                for (int q = 0; q < 16; q++) v[q] = 0.f;
            }
            #pragma unroll
            for (int q = 0; q < 16; q += 2) {
                __nv_bfloat16 h0, l0, h1, l1;
                split_bf16(v[q], h0, l0);
                split_bf16(v[q + 1], h1, l1);
                __nv_bfloat162 ph; ph.x = h0; ph.y = h1;
                __nv_bfloat162 pl; pl.x = l0; pl.y = l1;
                *(__nv_bfloat162*)&sAh[row][kb + q] = ph;
                *(__nv_bfloat162*)&sAl[row][kb + q] = pl;
            }
        }
        // ---- load B tile: W[k0..k0+31][bn..bn+127] -> transposed [n][k] hi/lo
        {
            const int k  = tid >> 3;
            const int nb = (tid & 7) * 16;
            const float4* wp = (const float4*)&Wr[(long)(k0 + k) * HF + bn + nb];
            float v[16];
            #pragma unroll
            for (int q = 0; q < 4; q++) *(float4*)&v[q * 4] = wp[q];
            #pragma unroll
            for (int q = 0; q < 16; q++) {
                __nv_bfloat16 h, l;
                split_bf16(v[q], h, l);
                sBh[nb + q][k] = h;
                sBl[nb + q][k] = l;
            }
        }
        __syncthreads();

        // ---- mma over two k16 fragments
        #pragma unroll
        for (int kf = 0; kf < 2; kf++) {
            const int kk = kf * 16;
            uint32_t bh[4][2], bl[4][2];
            #pragma unroll
            for (int ni = 0; ni < 4; ni++) {
                const int n = nband + ni * 8 + g;
                bh[ni][0] = *(const uint32_t*)&sBh[n][kk + t * 2];
                bh[ni][1] = *(const uint32_t*)&sBh[n][kk + t * 2 + 8];
                bl[ni][0] = *(const uint32_t*)&sBl[n][kk + t * 2];
                bl[ni][1] = *(const uint32_t*)&sBl[n][kk + t * 2 + 8];
            }
            #pragma unroll
            for (int mi = 0; mi < 4; mi++) {
                const int rowA = mband + mi * 16 + g;
                uint32_t ah[4], al[4];
                ah[0] = *(const uint32_t*)&sAh[rowA][kk + t * 2];
                ah[1] = *(const uint32_t*)&sAh[rowA + 8][kk + t * 2];
                ah[2] = *(const uint32_t*)&sAh[rowA][kk + t * 2 + 8];
                ah[3] = *(const uint32_t*)&sAh[rowA + 8][kk + t * 2 + 8];
                al[0] = *(const uint32_t*)&sAl[rowA][kk + t * 2];
                al[1] = *(const uint32_t*)&sAl[rowA + 8][kk + t * 2];
                al[2] = *(const uint32_t*)&sAl[rowA][kk + t * 2 + 8];
                al[3] = *(const uint32_t*)&sAl[rowA + 8][kk + t * 2 + 8];
                #pragma unroll
                for (int ni = 0; ni < 4; ni++) {
                    mma_bf16(acc[mi][ni], ah, bh[ni]);
                    mma_bf16(acc[mi][ni], ah, bl[ni]);
                    mma_bf16(acc[mi][ni], al, bh[ni]);
                }
            }
        }
    }

    // ---- epilogue: store z + fused el/er partials
    const int head = (bn + nband) >> 6;                // head for this warp's 32 cols
    float alc[4][2], arc[4][2];
    #pragma unroll
    for (int ni = 0; ni < 4; ni++)
        #pragma unroll
        for (int j = 0; j < 2; j++) {
            const int col = bn + nband + ni * 8 + t * 2 + j;   // within relation [0,256)
            alc[ni][j] = attn_l[r * HF + col];
            arc[ni][j] = attn_r[r * HF + col];
        }

    #pragma unroll
    for (int mi = 0; mi < 4; mi++) {
        #pragma unroll
        for (int rh = 0; rh < 2; rh++) {
            const int row = mband + mi * 16 + g + rh * 8;
            const int gr  = bm + row;
            const bool ok = (gr < NNODES);
            float sl = 0.f, sr = 0.f;
            #pragma unroll
            for (int ni = 0; ni < 4; ni++) {
                const float z0 = acc[mi][ni][rh * 2 + 0];
                const float z1 = acc[mi][ni][rh * 2 + 1];
                sl = fmaf(z0, alc[ni][0], sl); sl = fmaf(z1, alc[ni][1], sl);
                sr = fmaf(z0, arc[ni][0], sr); sr = fmaf(z1, arc[ni][1], sr);
                if (ok) {
                    const int col = bn + nband + ni * 8 + t * 2;
                    float2 zz = make_float2(z0, z1);
                    *(float2*)&g_z[((long)r * NNODES + gr) * HF + col] = zz;
                }
            }
            sl += __shfl_xor_sync(0xffffffffu, sl, 1);
            sl += __shfl_xor_sync(0xffffffffu, sl, 2);
            sr += __shfl_xor_sync(0xffffffffu, sr, 1);
            sr += __shfl_xor_sync(0xffffffffu, sr, 2);
            if (ok && t == 0) {
                atomicAdd(&g_el[((long)r * NNODES + gr) * HHEADS + head], sl);
                atomicAdd(&g_er[((long)r * NNODES + gr) * HHEADS + head], sr);
            }
        }
    }
}

// ---------------- edge pass 1: exp + den ----------------
__global__ void k_edge1(const int* __restrict__ src, const int* __restrict__ dst) {
    int e = blockIdx.x * blockDim.x + threadIdx.x;
    int r = blockIdx.y;
    if (e >= EEDGES) return;
    int s = src[(long)r * EEDGES + e];
    int d = dst[(long)r * EEDGES + e];
    float4 l  = *(const float4*)&g_el[((long)r * NNODES + s) * HHEADS];
    float4 rr = *(const float4*)&g_er[((long)r * NNODES + d) * HHEADS];
    float v0 = l.x + rr.x, v1 = l.y + rr.y, v2 = l.z + rr.z, v3 = l.w + rr.w;
    v0 = (v0 > 0.f) ? v0 : NEG_SLOPE * v0;
    v1 = (v1 > 0.f) ? v1 : NEG_SLOPE * v1;
    v2 = (v2 > 0.f) ? v2 : NEG_SLOPE * v2;
    v3 = (v3 > 0.f) ? v3 : NEG_SLOPE * v3;
    float4 ee = make_float4(expf(v0), expf(v1), expf(v2), expf(v3));
    *(float4*)&g_e[((long)r * EEDGES + e) * HHEADS] = ee;
    float* dp = &g_den[((long)r * NNODES + d) * HHEADS];
    atomicAdd(dp + 0, ee.x); atomicAdd(dp + 1, ee.y);
    atomicAdd(dp + 2, ee.z); atomicAdd(dp + 3, ee.w);
}

// ---------------- edge pass 2: scatter-aggregate ----------------
__global__ void k_edge3(const int* __restrict__ src, const int* __restrict__ dst,
                        float* __restrict__ out) {
    long gid = (long)blockIdx.x * blockDim.x + threadIdx.x;
    long warp = gid >> 5;
    int lane = threadIdx.x & 31;
    int r = blockIdx.y;
    if (warp >= EEDGES) return;
    int s = src[(long)r * EEDGES + warp];
    int d = dst[(long)r * EEDGES + warp];
    int h = lane >> 3;
    float alpha = g_e[((long)r * EEDGES + warp) * HHEADS + h] /
                  g_den[((long)r * NNODES + d) * HHEADS + h];
    const float4* zp = (const float4*)&g_z[((long)r * NNODES + s) * HF + lane * 8];
    float4 z0 = zp[0], z1 = zp[1];
    float4 v0 = make_float4(z0.x * alpha, z0.y * alpha, z0.z * alpha, z0.w * alpha);
    float4 v1 = make_float4(z1.x * alpha, z1.y * alpha, z1.z * alpha, z1.w * alpha);
    float* op = &out[(long)d * HF + lane * 8];
    atomicAdd((float4*)op,       v0);
    atomicAdd((float4*)(op + 4), v1);
}

// ---------------- final ELU ----------------
__global__ void k_elu(float* __restrict__ out, const float* __restrict__ bias) {
    int i = blockIdx.x * blockDim.x + threadIdx.x;
    if (i >= NNODES * HF) return;
    int c = i & 255;
    float b = bias[c] + bias[HF + c] + bias[2 * HF + c];
    float v = out[i] + b;
    out[i] = (v > 0.f) ? v : expm1f(v);
}

// ---------------- launch ----------------
extern "C" void kernel_launch(void* const* d_in, const int* in_sizes, int n_in,
                              void* d_out, int out_size) {
    const float* x      = (const float*)d_in[0];
    const float* W      = (const float*)d_in[1];
    const float* attn_l = (const float*)d_in[2];
    const float* attn_r = (const float*)d_in[3];
    const float* bias   = (const float*)d_in[4];
    const int*   src    = (const int*)d_in[5];
    const int*   dst    = (const int*)d_in[6];
    float* out = (float*)d_out;

    k_zero<<<1024, 256>>>(out);

    dim3 gg((NNODES + GBM - 1) / GBM, HF / GBN, RREL);   // 782 x 2 x 3
    k_gemm<<<gg, 256>>>(x, W, attn_l, attn_r);

    dim3 ge((EEDGES + 255) / 256, RREL);
    k_edge1<<<ge, 256>>>(src, dst);

    dim3 ge3((int)(((long)EEDGES * 32 + 255) / 256), RREL);
    k_edge3<<<ge3, 256>>>(src, dst, out);

    k_elu<<<(NNODES * HF + 255) / 256, 256>>>(out, bias);
}